// round 3
// baseline (speedup 1.0000x reference)
#include <cuda_runtime.h>
#include <cuda_bf16.h>
#include <cstdint>

// ---------------------------------------------------------------------------
// GraphAttentiveLinear: two independent blocks (m=1 and m=3), C=32, NI=1024.
// Pipeline per type:
//   K1: Gram(32x32) + clamp + LN1 + LeakyReLU  -> X   [N,1024] fp32
//   K2: H = X @ W1^T                            -> H   [N,1024] fp32
//   K3: LN2 + LeakyReLU                         -> X
//   K4: H = X @ W2^T + b2                       -> H
//   K5: row-group softmax (32 groups of 32) + attn @ v -> out
// Scratch: two static __device__ buffers (no allocations).
// ---------------------------------------------------------------------------

#define NROWS 100000
#define NI    1024
#define LN_EPS 1e-5f
#define SLOPE  0.01f

__device__ float g_bufA[(size_t)NROWS * NI];   // 409.6 MB
__device__ float g_bufB[(size_t)NROWS * NI];   // 409.6 MB

// ---------------------------------------------------------------------------
// K1: Gram + clamp + LN + LeakyReLU.  One block per row, 256 threads.
// ---------------------------------------------------------------------------
__global__ void gram_ln_lrelu_kernel(const float* __restrict__ V,
                                     const float* __restrict__ g,
                                     const float* __restrict__ b,
                                     float* __restrict__ X, int m) {
    int n = blockIdx.x;
    const float* v = V + (size_t)n * 32 * m;
    __shared__ float vs[96];
    __shared__ float red[16];
    int tid = threadIdx.x;
    if (tid < 32 * m) vs[tid] = v[tid];
    __syncthreads();

    float vals[4];
    float s = 0.f, s2 = 0.f;
#pragma unroll
    for (int i = 0; i < 4; i++) {
        int e = tid + i * 256;
        int a = e >> 5, c = e & 31;
        float d = 0.f;
        for (int k = 0; k < m; k++) d += vs[a * m + k] * vs[c * m + k];
        // sign(d) * max(|d|, 1e-12)  (sign(0)=0)
        if (d > 0.f)      d = fmaxf(d, 1e-12f);
        else if (d < 0.f) d = fminf(d, -1e-12f);
        vals[i] = d;
        s += d; s2 += d * d;
    }
#pragma unroll
    for (int o = 16; o > 0; o >>= 1) {
        s  += __shfl_xor_sync(0xffffffffu, s,  o);
        s2 += __shfl_xor_sync(0xffffffffu, s2, o);
    }
    if ((tid & 31) == 0) { red[tid >> 5] = s; red[8 + (tid >> 5)] = s2; }
    __syncthreads();
    if (tid < 32) {
        float a0 = (tid < 8) ? red[tid] : 0.f;
        float a1 = (tid < 8) ? red[8 + tid] : 0.f;
#pragma unroll
        for (int o = 4; o > 0; o >>= 1) {
            a0 += __shfl_xor_sync(0xffffffffu, a0, o);
            a1 += __shfl_xor_sync(0xffffffffu, a1, o);
        }
        if (tid == 0) { red[0] = a0; red[1] = a1; }
    }
    __syncthreads();
    float mean = red[0] * (1.f / NI);
    float var  = red[1] * (1.f / NI) - mean * mean;
    float rstd = rsqrtf(var + LN_EPS);
#pragma unroll
    for (int i = 0; i < 4; i++) {
        int e = tid + i * 256;
        float x = (vals[i] - mean) * rstd * g[e] + b[e];
        X[(size_t)n * NI + e] = (x >= 0.f) ? x : SLOPE * x;
    }
}

// ---------------------------------------------------------------------------
// K3: LayerNorm + LeakyReLU on a [N,1024] buffer.
// ---------------------------------------------------------------------------
__global__ void ln_lrelu_kernel(const float* __restrict__ in,
                                const float* __restrict__ g,
                                const float* __restrict__ b,
                                float* __restrict__ out) {
    int n = blockIdx.x;
    int tid = threadIdx.x;
    __shared__ float red[16];
    const float* row = in + (size_t)n * NI;

    float vals[4];
    float s = 0.f, s2 = 0.f;
#pragma unroll
    for (int i = 0; i < 4; i++) {
        float d = row[tid + i * 256];
        vals[i] = d;
        s += d; s2 += d * d;
    }
#pragma unroll
    for (int o = 16; o > 0; o >>= 1) {
        s  += __shfl_xor_sync(0xffffffffu, s,  o);
        s2 += __shfl_xor_sync(0xffffffffu, s2, o);
    }
    if ((tid & 31) == 0) { red[tid >> 5] = s; red[8 + (tid >> 5)] = s2; }
    __syncthreads();
    if (tid < 32) {
        float a0 = (tid < 8) ? red[tid] : 0.f;
        float a1 = (tid < 8) ? red[8 + tid] : 0.f;
#pragma unroll
        for (int o = 4; o > 0; o >>= 1) {
            a0 += __shfl_xor_sync(0xffffffffu, a0, o);
            a1 += __shfl_xor_sync(0xffffffffu, a1, o);
        }
        if (tid == 0) { red[0] = a0; red[1] = a1; }
    }
    __syncthreads();
    float mean = red[0] * (1.f / NI);
    float var  = red[1] * (1.f / NI) - mean * mean;
    float rstd = rsqrtf(var + LN_EPS);
#pragma unroll
    for (int i = 0; i < 4; i++) {
        int e = tid + i * 256;
        float x = (vals[i] - mean) * rstd * g[e] + b[e];
        out[(size_t)n * NI + e] = (x >= 0.f) ? x : SLOPE * x;
    }
}

// ---------------------------------------------------------------------------
// K2/K4: C[i,j] = sum_k A[i,k]*B[j,k]  (+bias[j]).  A:[M,1024], B:[1024,1024].
// Classic 128x128x8 tiling, 256 threads, 8x8 per thread.
// ---------------------------------------------------------------------------
#define BM 128
#define BN 128
#define BK 8
#define TM 8
#define TN 8

__global__ __launch_bounds__(256) void sgemm_abt_kernel(
    const float* __restrict__ A, const float* __restrict__ B,
    const float* __restrict__ bias, float* __restrict__ C, int M) {
    __shared__ float As[BK][BM];
    __shared__ float Bs[BK][BN];

    int tid  = threadIdx.x;
    int row0 = blockIdx.y * BM;
    int col0 = blockIdx.x * BN;

    int tx = tid & 15;   // 16 thread cols
    int ty = tid >> 4;   // 16 thread rows

    float acc[TM][TN];
#pragma unroll
    for (int i = 0; i < TM; i++)
#pragma unroll
        for (int j = 0; j < TN; j++) acc[i][j] = 0.f;

    int lrow = tid >> 1;          // 0..127
    int lk4  = (tid & 1) * 4;     // 0 or 4

    for (int k0 = 0; k0 < NI; k0 += BK) {
        float4 av = make_float4(0.f, 0.f, 0.f, 0.f);
        int ar = row0 + lrow;
        if (ar < M)
            av = *reinterpret_cast<const float4*>(A + (size_t)ar * NI + k0 + lk4);
        As[lk4 + 0][lrow] = av.x; As[lk4 + 1][lrow] = av.y;
        As[lk4 + 2][lrow] = av.z; As[lk4 + 3][lrow] = av.w;

        int br = col0 + lrow;
        float4 bv = *reinterpret_cast<const float4*>(B + (size_t)br * NI + k0 + lk4);
        Bs[lk4 + 0][lrow] = bv.x; Bs[lk4 + 1][lrow] = bv.y;
        Bs[lk4 + 2][lrow] = bv.z; Bs[lk4 + 3][lrow] = bv.w;
        __syncthreads();

#pragma unroll
        for (int kk = 0; kk < BK; kk++) {
            float ra[TM], rb[TN];
#pragma unroll
            for (int i = 0; i < TM; i++) ra[i] = As[kk][ty * TM + i];
#pragma unroll
            for (int j = 0; j < TN; j++) rb[j] = Bs[kk][tx * TN + j];
#pragma unroll
            for (int i = 0; i < TM; i++)
#pragma unroll
                for (int j = 0; j < TN; j++) acc[i][j] += ra[i] * rb[j];
        }
        __syncthreads();
    }

#pragma unroll
    for (int i = 0; i < TM; i++) {
        int r = row0 + ty * TM + i;
        if (r >= M) continue;
#pragma unroll
        for (int j = 0; j < TN; j++) {
            int c = col0 + tx * TN + j;
            float v = acc[i][j];
            if (bias) v += bias[c];
            C[(size_t)r * NI + c] = v;
        }
    }
}

// ---------------------------------------------------------------------------
// K5: softmax over 32 groups of 32 + attn @ v.  One block per row, 8 warps.
// ---------------------------------------------------------------------------
__global__ void softmax_out_kernel(const float* __restrict__ H,
                                   const float* __restrict__ V,
                                   float* __restrict__ out, int m) {
    int n = blockIdx.x;
    __shared__ float vs[96];
    int tid = threadIdx.x, w = tid >> 5, lane = tid & 31;
    if (tid < 32 * m) vs[tid] = V[(size_t)n * 32 * m + tid];
    __syncthreads();
    const float* h = H + (size_t)n * NI;
#pragma unroll
    for (int it = 0; it < 4; it++) {
        int a = w + it * 8;
        float x = h[a * 32 + lane];
        float mx = x;
#pragma unroll
        for (int o = 16; o > 0; o >>= 1)
            mx = fmaxf(mx, __shfl_xor_sync(0xffffffffu, mx, o));
        float e = __expf(x - mx);
        float sum = e;
#pragma unroll
        for (int o = 16; o > 0; o >>= 1)
            sum += __shfl_xor_sync(0xffffffffu, sum, o);
        float p = e / sum;
        for (int k = 0; k < m; k++) {
            float t = p * vs[lane * m + k];
#pragma unroll
            for (int o = 16; o > 0; o >>= 1)
                t += __shfl_xor_sync(0xffffffffu, t, o);
            if (lane == 0) out[(size_t)n * 32 * m + a * m + k] = t;
        }
    }
}

// ---------------------------------------------------------------------------
// Launch
// ---------------------------------------------------------------------------
extern "C" void kernel_launch(void* const* d_in, const int* in_sizes, int n_in,
                              void* d_out, int out_size) {
    const float* f0 = (const float*)d_in[0];
    const float* f1 = (const float*)d_in[1];
    // type 0 params
    const float* ln1_g_0 = (const float*)d_in[2];
    const float* ln1_b_0 = (const float*)d_in[3];
    const float* w1_0    = (const float*)d_in[4];
    const float* ln2_g_0 = (const float*)d_in[5];
    const float* ln2_b_0 = (const float*)d_in[6];
    const float* w2_0    = (const float*)d_in[7];
    const float* b2_0    = (const float*)d_in[8];
    // type 1 params
    const float* ln1_g_1 = (const float*)d_in[9];
    const float* ln1_b_1 = (const float*)d_in[10];
    const float* w1_1    = (const float*)d_in[11];
    const float* ln2_g_1 = (const float*)d_in[12];
    const float* ln2_b_1 = (const float*)d_in[13];
    const float* w2_1    = (const float*)d_in[14];
    const float* b2_1    = (const float*)d_in[15];

    float* out = (float*)d_out;

    float *pA = nullptr, *pB = nullptr;
    cudaGetSymbolAddress((void**)&pA, g_bufA);
    cudaGetSymbolAddress((void**)&pB, g_bufB);

    dim3 gemm_grid(NI / BN, (NROWS + BM - 1) / BM);

    // ---- type 0 (m = 1), output at offset 0 ----
    gram_ln_lrelu_kernel<<<NROWS, 256>>>(f0, ln1_g_0, ln1_b_0, pA, 1);
    sgemm_abt_kernel<<<gemm_grid, 256>>>(pA, w1_0, nullptr, pB, NROWS);
    ln_lrelu_kernel<<<NROWS, 256>>>(pB, ln2_g_0, ln2_b_0, pA);
    sgemm_abt_kernel<<<gemm_grid, 256>>>(pA, w2_0, b2_0, pB, NROWS);
    softmax_out_kernel<<<NROWS, 256>>>(pB, f0, out, 1);

    // ---- type 1 (m = 3), output at offset NROWS*32 ----
    gram_ln_lrelu_kernel<<<NROWS, 256>>>(f1, ln1_g_1, ln1_b_1, pA, 3);
    sgemm_abt_kernel<<<gemm_grid, 256>>>(pA, w1_1, nullptr, pB, NROWS);
    ln_lrelu_kernel<<<NROWS, 256>>>(pB, ln2_g_1, ln2_b_1, pA);
    sgemm_abt_kernel<<<gemm_grid, 256>>>(pA, w2_1, b2_1, pB, NROWS);
    softmax_out_kernel<<<NROWS, 256>>>(pB, f1, out + (size_t)NROWS * 32, 3);
}

// round 11
// speedup vs baseline: 2.5434x; 2.5434x over previous
#include <cuda_runtime.h>
#include <cuda_bf16.h>
#include <cstdint>

// ---------------------------------------------------------------------------
// GraphAttentiveLinear on GB300 — portable tensor-core path.
// tcgen05 is unavailable (harness lowers PTX to .target sm_103, no 'a'
// feature), so GEMMs use mma.sync.m16n8k16 bf16 (HMMA) with split-bf16
// (hi/lo, 3 MMAs) for fp32-class accuracy, cp.async double buffering.
// ---------------------------------------------------------------------------

#define NROWS 100000
#define NI    1024
#define LN_EPS 1e-5f
#define SLOPE  0.01f

__device__ __nv_bfloat16 g_Xhi[(size_t)NROWS * NI];   // 204.8 MB
__device__ __nv_bfloat16 g_Xlo[(size_t)NROWS * NI];   // 204.8 MB
__device__ float         g_H  [(size_t)NROWS * NI];   // 409.6 MB
__device__ __nv_bfloat16 g_Whi[(size_t)NI * NI];      // 2 MB
__device__ __nv_bfloat16 g_Wlo[(size_t)NI * NI];      // 2 MB

// ------------------------------- PTX helpers -------------------------------
__device__ __forceinline__ uint32_t smem_u32(const void* p) {
    uint32_t a;
    asm("{ .reg .u64 t; cvta.to.shared.u64 t, %1; cvt.u32.u64 %0, t; }"
        : "=r"(a) : "l"(p));
    return a;
}

#define CP_ASYNC(dst, src, ssz) \
    asm volatile("cp.async.cg.shared.global [%0], [%1], 16, %2;" \
                 :: "r"(dst), "l"(src), "r"(ssz))
#define CP_COMMIT() asm volatile("cp.async.commit_group;" ::: "memory")
#define CP_WAIT1()  asm volatile("cp.async.wait_group 1;" ::: "memory")
#define CP_WAIT0()  asm volatile("cp.async.wait_group 0;" ::: "memory")

__device__ __forceinline__ void ldsm_x4(uint32_t& r0, uint32_t& r1,
                                        uint32_t& r2, uint32_t& r3, uint32_t a) {
    asm volatile("ldmatrix.sync.aligned.m8n8.x4.shared.b16 {%0,%1,%2,%3}, [%4];"
                 : "=r"(r0), "=r"(r1), "=r"(r2), "=r"(r3) : "r"(a));
}
__device__ __forceinline__ void ldsm_x2(uint32_t& r0, uint32_t& r1, uint32_t a) {
    asm volatile("ldmatrix.sync.aligned.m8n8.x2.shared.b16 {%0,%1}, [%2];"
                 : "=r"(r0), "=r"(r1) : "r"(a));
}
__device__ __forceinline__ void mma16816(float* d, const uint32_t* a,
                                         uint32_t b0, uint32_t b1) {
    asm volatile("mma.sync.aligned.m16n8k16.row.col.f32.bf16.bf16.f32 "
                 "{%0,%1,%2,%3},{%4,%5,%6,%7},{%8,%9},{%0,%1,%2,%3};"
                 : "+f"(d[0]), "+f"(d[1]), "+f"(d[2]), "+f"(d[3])
                 : "r"(a[0]), "r"(a[1]), "r"(a[2]), "r"(a[3]), "r"(b0), "r"(b1));
}

// ------------------------- GEMM tile configuration -------------------------
#define BM 128
#define BN 256
#define BKC 32
#define NITER (NI / BKC)          // 32
#define PITCH 40                  // bf16 elements per smem row (80B, conflict-free)
#define STG_A 10240               // 128*40*2 bytes
#define STG_B 20480               // 256*40*2 bytes
#define OFF_AH 0
#define OFF_AL (STG_A)
#define OFF_BH (2*STG_A)
#define OFF_BL (2*STG_A + STG_B)
#define STAGE_BYTES (2*STG_A + 2*STG_B)     // 61440
#define SMEM_TOTAL (2 * STAGE_BYTES)        // 122880

// ---------------------------------------------------------------------------
// GEMM: C[i,j] = sum_k A[i,k]*B[j,k] (+bias[j]); A,B given as bf16 hi/lo pairs.
// 256 threads, 8 warps (2x4), warp tile 64x64, double-buffered cp.async.
// ---------------------------------------------------------------------------
__global__ void __launch_bounds__(256) gemm_mma_kernel(
    const __nv_bfloat16* __restrict__ Ahi, const __nv_bfloat16* __restrict__ Alo,
    const __nv_bfloat16* __restrict__ Bhi, const __nv_bfloat16* __restrict__ Blo,
    const float* __restrict__ bias, float* __restrict__ C, int M) {
    extern __shared__ char smem[];
    const uint32_t sbase = smem_u32(smem);
    const int tid = threadIdx.x;
    const int lane = tid & 31;
    const int wid = tid >> 5;
    const int wm = wid & 1;        // 0..1 -> m offset wm*64
    const int wn = wid >> 1;       // 0..3 -> n offset wn*64
    const int row0 = blockIdx.y * BM;
    const int col0 = blockIdx.x * BN;

    float acc[4][8][4];
#pragma unroll
    for (int i = 0; i < 4; i++)
#pragma unroll
        for (int j = 0; j < 8; j++)
#pragma unroll
            for (int q = 0; q < 4; q++) acc[i][j][q] = 0.f;

    // ---- async stage loader ----
    auto load_stage = [&](int stage, int it) {
        const uint32_t sb = sbase + stage * STAGE_BYTES;
        const int k0 = it * BKC;
        // A tiles: 512 16B-chunks each (hi, lo); 2 per thread
#pragma unroll
        for (int q = 0; q < 2; q++) {
            int c = tid + q * 256;
            int r = c >> 2, k8 = (c & 3) * 8;
            int gr = row0 + r;
            int grc = (gr < M) ? gr : (M - 1);
            int ssz = (gr < M) ? 16 : 0;
            size_t go = (size_t)grc * NI + k0 + k8;
            uint32_t doff = (uint32_t)(r * PITCH + k8) * 2;
            CP_ASYNC(sb + OFF_AH + doff, Ahi + go, ssz);
            CP_ASYNC(sb + OFF_AL + doff, Alo + go, ssz);
        }
        // B tiles: 1024 chunks each (hi, lo); 4 per thread
#pragma unroll
        for (int q = 0; q < 4; q++) {
            int c = tid + q * 256;
            int n = c >> 2, k8 = (c & 3) * 8;
            size_t go = (size_t)(col0 + n) * NI + k0 + k8;
            uint32_t doff = (uint32_t)(n * PITCH + k8) * 2;
            CP_ASYNC(sb + OFF_BH + doff, Bhi + go, 16);
            CP_ASYNC(sb + OFF_BL + doff, Blo + go, 16);
        }
        CP_COMMIT();
    };

    // ---- compute on one resident stage ----
    const int l16 = lane & 15, kh = lane >> 4;        // A ldmatrix addressing
    const int l8 = lane & 7, k2 = (lane >> 3) & 1;    // B ldmatrix addressing
    auto compute_stage = [&](int stage) {
        const uint32_t sb = sbase + stage * STAGE_BYTES;
#pragma unroll
        for (int ks = 0; ks < 2; ks++) {
            uint32_t ah[4][4], al[4][4];
#pragma unroll
            for (int i = 0; i < 4; i++) {
                uint32_t ao = (uint32_t)((wm * 64 + i * 16 + l16) * PITCH
                                         + ks * 16 + kh * 8) * 2;
                ldsm_x4(ah[i][0], ah[i][1], ah[i][2], ah[i][3], sb + OFF_AH + ao);
                ldsm_x4(al[i][0], al[i][1], al[i][2], al[i][3], sb + OFF_AL + ao);
            }
#pragma unroll
            for (int j = 0; j < 8; j++) {
                uint32_t bo = (uint32_t)((wn * 64 + j * 8 + l8) * PITCH
                                         + ks * 16 + k2 * 8) * 2;
                uint32_t bh0, bh1, bl0, bl1;
                ldsm_x2(bh0, bh1, sb + OFF_BH + bo);
                ldsm_x2(bl0, bl1, sb + OFF_BL + bo);
#pragma unroll
                for (int i = 0; i < 4; i++) {
                    mma16816(acc[i][j], ah[i], bh0, bh1);   // hi*hi
                    mma16816(acc[i][j], ah[i], bl0, bl1);   // hi*lo
                    mma16816(acc[i][j], al[i], bh0, bh1);   // lo*hi
                }
            }
        }
    };

    // ---- main pipeline ----
    load_stage(0, 0);
    for (int it = 0; it < NITER; it++) {
        if (it + 1 < NITER) {
            load_stage((it + 1) & 1, it + 1);
            CP_WAIT1();
        } else {
            CP_WAIT0();
        }
        __syncthreads();
        compute_stage(it & 1);
        __syncthreads();
    }

    // ---- epilogue ----
    const int tr = lane >> 2, tc = (lane & 3) * 2;
#pragma unroll
    for (int i = 0; i < 4; i++) {
        int rb = row0 + wm * 64 + i * 16 + tr;
#pragma unroll
        for (int j = 0; j < 8; j++) {
            int cc = col0 + wn * 64 + j * 8 + tc;
            float b0 = bias ? bias[cc] : 0.f;
            float b1 = bias ? bias[cc + 1] : 0.f;
            if (rb < M) {
                float2 v = make_float2(acc[i][j][0] + b0, acc[i][j][1] + b1);
                *reinterpret_cast<float2*>(C + (size_t)rb * NI + cc) = v;
            }
            if (rb + 8 < M) {
                float2 v = make_float2(acc[i][j][2] + b0, acc[i][j][3] + b1);
                *reinterpret_cast<float2*>(C + (size_t)(rb + 8) * NI + cc) = v;
            }
        }
    }
}

// ---------------------------------------------------------------------------
// Weight split: W fp32 -> (hi, lo) bf16.
// ---------------------------------------------------------------------------
__global__ void wsplit_kernel(const float* __restrict__ W,
                              __nv_bfloat16* __restrict__ hi,
                              __nv_bfloat16* __restrict__ lo) {
    int i = (blockIdx.x * 256 + threadIdx.x) * 4;
    float4 w = *reinterpret_cast<const float4*>(W + i);
    __nv_bfloat16 h0 = __float2bfloat16(w.x), h1 = __float2bfloat16(w.y);
    __nv_bfloat16 h2 = __float2bfloat16(w.z), h3 = __float2bfloat16(w.w);
    __nv_bfloat162 hh0 = {h0, h1}, hh1 = {h2, h3};
    *reinterpret_cast<__nv_bfloat162*>(hi + i)     = hh0;
    *reinterpret_cast<__nv_bfloat162*>(hi + i + 2) = hh1;
    __nv_bfloat162 ll0 = {__float2bfloat16(w.x - __bfloat162float(h0)),
                          __float2bfloat16(w.y - __bfloat162float(h1))};
    __nv_bfloat162 ll1 = {__float2bfloat16(w.z - __bfloat162float(h2)),
                          __float2bfloat16(w.w - __bfloat162float(h3))};
    *reinterpret_cast<__nv_bfloat162*>(lo + i)     = ll0;
    *reinterpret_cast<__nv_bfloat162*>(lo + i + 2) = ll1;
}

__device__ __forceinline__ void store_hilo(__nv_bfloat16* hi, __nv_bfloat16* lo,
                                           size_t idx, float x) {
    __nv_bfloat16 h = __float2bfloat16(x);
    hi[idx] = h;
    lo[idx] = __float2bfloat16(x - __bfloat162float(h));
}

// ---------------------------------------------------------------------------
// K1: Gram + clamp + LN + LeakyReLU -> bf16 hi/lo.
// ---------------------------------------------------------------------------
__global__ void gram_ln_lrelu_kernel(const float* __restrict__ V,
                                     const float* __restrict__ g,
                                     const float* __restrict__ b,
                                     __nv_bfloat16* __restrict__ Xhi,
                                     __nv_bfloat16* __restrict__ Xlo, int m) {
    int n = blockIdx.x;
    const float* v = V + (size_t)n * 32 * m;
    __shared__ float vs[96];
    __shared__ float red[16];
    int tid = threadIdx.x;
    if (tid < 32 * m) vs[tid] = v[tid];
    __syncthreads();

    float vals[4];
    float s = 0.f, s2 = 0.f;
#pragma unroll
    for (int i = 0; i < 4; i++) {
        int e = tid + i * 256;
        int a = e >> 5, c = e & 31;
        float d = 0.f;
        for (int k = 0; k < m; k++) d += vs[a * m + k] * vs[c * m + k];
        if (d > 0.f)      d = fmaxf(d, 1e-12f);
        else if (d < 0.f) d = fminf(d, -1e-12f);
        vals[i] = d;
        s += d; s2 += d * d;
    }
#pragma unroll
    for (int o = 16; o > 0; o >>= 1) {
        s  += __shfl_xor_sync(0xffffffffu, s,  o);
        s2 += __shfl_xor_sync(0xffffffffu, s2, o);
    }
    if ((tid & 31) == 0) { red[tid >> 5] = s; red[8 + (tid >> 5)] = s2; }
    __syncthreads();
    if (tid < 32) {
        float a0 = (tid < 8) ? red[tid] : 0.f;
        float a1 = (tid < 8) ? red[8 + tid] : 0.f;
#pragma unroll
        for (int o = 4; o > 0; o >>= 1) {
            a0 += __shfl_xor_sync(0xffffffffu, a0, o);
            a1 += __shfl_xor_sync(0xffffffffu, a1, o);
        }
        if (tid == 0) { red[0] = a0; red[1] = a1; }
    }
    __syncthreads();
    float mean = red[0] * (1.f / NI);
    float var  = red[1] * (1.f / NI) - mean * mean;
    float rstd = rsqrtf(var + LN_EPS);
#pragma unroll
    for (int i = 0; i < 4; i++) {
        int e = tid + i * 256;
        float x = (vals[i] - mean) * rstd * g[e] + b[e];
        x = (x >= 0.f) ? x : SLOPE * x;
        store_hilo(Xhi, Xlo, (size_t)n * NI + e, x);
    }
}

// ---------------------------------------------------------------------------
// K3: LayerNorm + LeakyReLU (fp32 in) -> bf16 hi/lo.
// ---------------------------------------------------------------------------
__global__ void ln_lrelu_kernel(const float* __restrict__ in,
                                const float* __restrict__ g,
                                const float* __restrict__ b,
                                __nv_bfloat16* __restrict__ Xhi,
                                __nv_bfloat16* __restrict__ Xlo) {
    int n = blockIdx.x;
    int tid = threadIdx.x;
    __shared__ float red[16];
    const float* row = in + (size_t)n * NI;

    float vals[4];
    float s = 0.f, s2 = 0.f;
#pragma unroll
    for (int i = 0; i < 4; i++) {
        float d = row[tid + i * 256];
        vals[i] = d;
        s += d; s2 += d * d;
    }
#pragma unroll
    for (int o = 16; o > 0; o >>= 1) {
        s  += __shfl_xor_sync(0xffffffffu, s,  o);
        s2 += __shfl_xor_sync(0xffffffffu, s2, o);
    }
    if ((tid & 31) == 0) { red[tid >> 5] = s; red[8 + (tid >> 5)] = s2; }
    __syncthreads();
    if (tid < 32) {
        float a0 = (tid < 8) ? red[tid] : 0.f;
        float a1 = (tid < 8) ? red[8 + tid] : 0.f;
#pragma unroll
        for (int o = 4; o > 0; o >>= 1) {
            a0 += __shfl_xor_sync(0xffffffffu, a0, o);
            a1 += __shfl_xor_sync(0xffffffffu, a1, o);
        }
        if (tid == 0) { red[0] = a0; red[1] = a1; }
    }
    __syncthreads();
    float mean = red[0] * (1.f / NI);
    float var  = red[1] * (1.f / NI) - mean * mean;
    float rstd = rsqrtf(var + LN_EPS);
#pragma unroll
    for (int i = 0; i < 4; i++) {
        int e = tid + i * 256;
        float x = (vals[i] - mean) * rstd * g[e] + b[e];
        x = (x >= 0.f) ? x : SLOPE * x;
        store_hilo(Xhi, Xlo, (size_t)n * NI + e, x);
    }
}

// ---------------------------------------------------------------------------
// K5: softmax over 32 groups of 32 + attn @ v.
// ---------------------------------------------------------------------------
__global__ void softmax_out_kernel(const float* __restrict__ H,
                                   const float* __restrict__ V,
                                   float* __restrict__ out, int m) {
    int n = blockIdx.x;
    __shared__ float vs[96];
    int tid = threadIdx.x, w = tid >> 5, lane = tid & 31;
    if (tid < 32 * m) vs[tid] = V[(size_t)n * 32 * m + tid];
    __syncthreads();
    const float* h = H + (size_t)n * NI;
#pragma unroll
    for (int it = 0; it < 4; it++) {
        int a = w + it * 8;
        float x = h[a * 32 + lane];
        float mx = x;
#pragma unroll
        for (int o = 16; o > 0; o >>= 1)
            mx = fmaxf(mx, __shfl_xor_sync(0xffffffffu, mx, o));
        float e = __expf(x - mx);
        float sum = e;
#pragma unroll
        for (int o = 16; o > 0; o >>= 1)
            sum += __shfl_xor_sync(0xffffffffu, sum, o);
        float p = e / sum;
        for (int k = 0; k < m; k++) {
            float t = p * vs[lane * m + k];
#pragma unroll
            for (int o = 16; o > 0; o >>= 1)
                t += __shfl_xor_sync(0xffffffffu, t, o);
            if (lane == 0) out[(size_t)n * 32 * m + a * m + k] = t;
        }
    }
}

// ---------------------------------------------------------------------------
// Launch
// ---------------------------------------------------------------------------
extern "C" void kernel_launch(void* const* d_in, const int* in_sizes, int n_in,
                              void* d_out, int out_size) {
    const float* f0 = (const float*)d_in[0];
    const float* f1 = (const float*)d_in[1];
    const float* ln1_g_0 = (const float*)d_in[2];
    const float* ln1_b_0 = (const float*)d_in[3];
    const float* w1_0    = (const float*)d_in[4];
    const float* ln2_g_0 = (const float*)d_in[5];
    const float* ln2_b_0 = (const float*)d_in[6];
    const float* w2_0    = (const float*)d_in[7];
    const float* b2_0    = (const float*)d_in[8];
    const float* ln1_g_1 = (const float*)d_in[9];
    const float* ln1_b_1 = (const float*)d_in[10];
    const float* w1_1    = (const float*)d_in[11];
    const float* ln2_g_1 = (const float*)d_in[12];
    const float* ln2_b_1 = (const float*)d_in[13];
    const float* w2_1    = (const float*)d_in[14];
    const float* b2_1    = (const float*)d_in[15];

    float* out = (float*)d_out;

    __nv_bfloat16 *xhi, *xlo, *whi, *wlo;
    float* hbuf;
    cudaGetSymbolAddress((void**)&xhi, g_Xhi);
    cudaGetSymbolAddress((void**)&xlo, g_Xlo);
    cudaGetSymbolAddress((void**)&whi, g_Whi);
    cudaGetSymbolAddress((void**)&wlo, g_Wlo);
    cudaGetSymbolAddress((void**)&hbuf, g_H);

    cudaFuncSetAttribute(gemm_mma_kernel,
                         cudaFuncAttributeMaxDynamicSharedMemorySize, SMEM_TOTAL);

    dim3 gemm_grid(NI / BN, (NROWS + BM - 1) / BM);

    // ---- type 0 (m = 1) ----
    wsplit_kernel<<<NI * NI / 1024, 256>>>(w1_0, whi, wlo);
    gram_ln_lrelu_kernel<<<NROWS, 256>>>(f0, ln1_g_0, ln1_b_0, xhi, xlo, 1);
    gemm_mma_kernel<<<gemm_grid, 256, SMEM_TOTAL>>>(xhi, xlo, whi, wlo, nullptr, hbuf, NROWS);
    wsplit_kernel<<<NI * NI / 1024, 256>>>(w2_0, whi, wlo);
    ln_lrelu_kernel<<<NROWS, 256>>>(hbuf, ln2_g_0, ln2_b_0, xhi, xlo);
    gemm_mma_kernel<<<gemm_grid, 256, SMEM_TOTAL>>>(xhi, xlo, whi, wlo, b2_0, hbuf, NROWS);
    softmax_out_kernel<<<NROWS, 256>>>(hbuf, f0, out, 1);

    // ---- type 1 (m = 3) ----
    wsplit_kernel<<<NI * NI / 1024, 256>>>(w1_1, whi, wlo);
    gram_ln_lrelu_kernel<<<NROWS, 256>>>(f1, ln1_g_1, ln1_b_1, xhi, xlo, 3);
    gemm_mma_kernel<<<gemm_grid, 256, SMEM_TOTAL>>>(xhi, xlo, whi, wlo, nullptr, hbuf, NROWS);
    wsplit_kernel<<<NI * NI / 1024, 256>>>(w2_1, whi, wlo);
    ln_lrelu_kernel<<<NROWS, 256>>>(hbuf, ln2_g_1, ln2_b_1, xhi, xlo);
    gemm_mma_kernel<<<gemm_grid, 256, SMEM_TOTAL>>>(xhi, xlo, whi, wlo, b2_1, hbuf, NROWS);
    softmax_out_kernel<<<NROWS, 256>>>(hbuf, f1, out + (size_t)NROWS * 32, 3);
}

// round 13
// speedup vs baseline: 2.7484x; 1.0806x over previous
#include <cuda_runtime.h>
#include <cuda_bf16.h>
#include <cstdint>

// ---------------------------------------------------------------------------
// GraphAttentiveLinear on GB300 — portable tensor-core path (HMMA).
// R12: BN 256->128, acc 64x32/warp, <=128 regs, 2 CTAs/SM co-residency.
// ---------------------------------------------------------------------------

#define NROWS 100000
#define NI    1024
#define LN_EPS 1e-5f
#define SLOPE  0.01f

__device__ __nv_bfloat16 g_Xhi[(size_t)NROWS * NI];   // 204.8 MB
__device__ __nv_bfloat16 g_Xlo[(size_t)NROWS * NI];   // 204.8 MB
__device__ float         g_H  [(size_t)NROWS * NI];   // 409.6 MB
__device__ __nv_bfloat16 g_Whi[(size_t)NI * NI];      // 2 MB
__device__ __nv_bfloat16 g_Wlo[(size_t)NI * NI];      // 2 MB

// ------------------------------- PTX helpers -------------------------------
__device__ __forceinline__ uint32_t smem_u32(const void* p) {
    uint32_t a;
    asm("{ .reg .u64 t; cvta.to.shared.u64 t, %1; cvt.u32.u64 %0, t; }"
        : "=r"(a) : "l"(p));
    return a;
}

#define CP_ASYNC(dst, src, ssz) \
    asm volatile("cp.async.cg.shared.global [%0], [%1], 16, %2;" \
                 :: "r"(dst), "l"(src), "r"(ssz))
#define CP_COMMIT() asm volatile("cp.async.commit_group;" ::: "memory")
#define CP_WAIT1()  asm volatile("cp.async.wait_group 1;" ::: "memory")
#define CP_WAIT0()  asm volatile("cp.async.wait_group 0;" ::: "memory")

__device__ __forceinline__ void ldsm_x4(uint32_t& r0, uint32_t& r1,
                                        uint32_t& r2, uint32_t& r3, uint32_t a) {
    asm volatile("ldmatrix.sync.aligned.m8n8.x4.shared.b16 {%0,%1,%2,%3}, [%4];"
                 : "=r"(r0), "=r"(r1), "=r"(r2), "=r"(r3) : "r"(a));
}
__device__ __forceinline__ void ldsm_x2(uint32_t& r0, uint32_t& r1, uint32_t a) {
    asm volatile("ldmatrix.sync.aligned.m8n8.x2.shared.b16 {%0,%1}, [%2];"
                 : "=r"(r0), "=r"(r1) : "r"(a));
}
__device__ __forceinline__ void mma16816(float* d, const uint32_t* a,
                                         uint32_t b0, uint32_t b1) {
    asm volatile("mma.sync.aligned.m16n8k16.row.col.f32.bf16.bf16.f32 "
                 "{%0,%1,%2,%3},{%4,%5,%6,%7},{%8,%9},{%0,%1,%2,%3};"
                 : "+f"(d[0]), "+f"(d[1]), "+f"(d[2]), "+f"(d[3])
                 : "r"(a[0]), "r"(a[1]), "r"(a[2]), "r"(a[3]), "r"(b0), "r"(b1));
}

// ------------------------- GEMM tile configuration -------------------------
#define BM 128
#define BN 128
#define BKC 32
#define NITER (NI / BKC)          // 32
#define PITCH 40                  // bf16 per smem row (80B, conflict-free ldmatrix)
#define STG_T 10240               // 128*40*2 bytes (one tensor tile)
#define OFF_AH 0
#define OFF_AL (STG_T)
#define OFF_BH (2*STG_T)
#define OFF_BL (3*STG_T)
#define STAGE_BYTES (4*STG_T)     // 40960
#define SMEM_TOTAL (2 * STAGE_BYTES)   // 81920 -> 2 CTAs/SM

// ---------------------------------------------------------------------------
// GEMM: C[i,j] = sum_k A[i,k]*B[j,k] (+bias[j]); split-bf16 (3 MMAs).
// 256 threads, 8 warps (2 row x 4 col), warp tile 64x32, double-buffered.
// ---------------------------------------------------------------------------
__global__ void __launch_bounds__(256, 2) gemm_mma_kernel(
    const __nv_bfloat16* __restrict__ Ahi, const __nv_bfloat16* __restrict__ Alo,
    const __nv_bfloat16* __restrict__ Bhi, const __nv_bfloat16* __restrict__ Blo,
    const float* __restrict__ bias, float* __restrict__ C, int M) {
    extern __shared__ char smem[];
    const uint32_t sbase = smem_u32(smem);
    const int tid = threadIdx.x;
    const int lane = tid & 31;
    const int wid = tid >> 5;
    const int wm = wid & 1;        // row group: wm*64
    const int wn = wid >> 1;       // col group: wn*32
    const int row0 = blockIdx.y * BM;
    const int col0 = blockIdx.x * BN;

    float acc[4][4][4];
#pragma unroll
    for (int i = 0; i < 4; i++)
#pragma unroll
        for (int j = 0; j < 4; j++)
#pragma unroll
            for (int q = 0; q < 4; q++) acc[i][j][q] = 0.f;

    // ---- async stage loader: A and B tiles are both 128 rows x 32 bf16 ----
    auto load_stage = [&](int stage, int it) {
        const uint32_t sb = sbase + stage * STAGE_BYTES;
        const int k0 = it * BKC;
#pragma unroll
        for (int q = 0; q < 2; q++) {
            int c = tid + q * 256;         // 0..511
            int r = c >> 2, k8 = (c & 3) * 8;
            uint32_t doff = (uint32_t)(r * PITCH + k8) * 2;
            // A (bounds-checked on M)
            int gr = row0 + r;
            int grc = (gr < M) ? gr : (M - 1);
            int ssz = (gr < M) ? 16 : 0;
            size_t goA = (size_t)grc * NI + k0 + k8;
            CP_ASYNC(sb + OFF_AH + doff, Ahi + goA, ssz);
            CP_ASYNC(sb + OFF_AL + doff, Alo + goA, ssz);
            // B (always in range: NI x NI weight)
            size_t goB = (size_t)(col0 + r) * NI + k0 + k8;
            CP_ASYNC(sb + OFF_BH + doff, Bhi + goB, 16);
            CP_ASYNC(sb + OFF_BL + doff, Blo + goB, 16);
        }
        CP_COMMIT();
    };

    // ---- compute on one resident stage ----
    const int l16 = lane & 15, kh = lane >> 4;        // A ldmatrix addressing
    const int l8 = lane & 7, k2 = (lane >> 3) & 1;    // B ldmatrix addressing
    auto compute_stage = [&](int stage) {
        const uint32_t sb = sbase + stage * STAGE_BYTES;
#pragma unroll
        for (int ks = 0; ks < 2; ks++) {
            // B fragments for this ks (4 col sub-tiles, hi+lo)
            uint32_t bh[4][2], bl[4][2];
#pragma unroll
            for (int j = 0; j < 4; j++) {
                uint32_t bo = (uint32_t)((wn * 32 + j * 8 + l8) * PITCH
                                         + ks * 16 + k2 * 8) * 2;
                ldsm_x2(bh[j][0], bh[j][1], sb + OFF_BH + bo);
                ldsm_x2(bl[j][0], bl[j][1], sb + OFF_BL + bo);
            }
            // stream A fragments per 16-row sub-tile
#pragma unroll
            for (int i = 0; i < 4; i++) {
                uint32_t ah[4], al[4];
                uint32_t ao = (uint32_t)((wm * 64 + i * 16 + l16) * PITCH
                                         + ks * 16 + kh * 8) * 2;
                ldsm_x4(ah[0], ah[1], ah[2], ah[3], sb + OFF_AH + ao);
                ldsm_x4(al[0], al[1], al[2], al[3], sb + OFF_AL + ao);
#pragma unroll
                for (int j = 0; j < 4; j++) {
                    mma16816(acc[i][j], ah, bh[j][0], bh[j][1]);   // hi*hi
                    mma16816(acc[i][j], ah, bl[j][0], bl[j][1]);   // hi*lo
                    mma16816(acc[i][j], al, bh[j][0], bh[j][1]);   // lo*hi
                }
            }
        }
    };

    // ---- main pipeline ----
    load_stage(0, 0);
    for (int it = 0; it < NITER; it++) {
        if (it + 1 < NITER) {
            load_stage((it + 1) & 1, it + 1);
            CP_WAIT1();
        } else {
            CP_WAIT0();
        }
        __syncthreads();
        compute_stage(it & 1);
        __syncthreads();
    }

    // ---- epilogue ----
    const int tr = lane >> 2, tc = (lane & 3) * 2;
#pragma unroll
    for (int i = 0; i < 4; i++) {
        int rb = row0 + wm * 64 + i * 16 + tr;
#pragma unroll
        for (int j = 0; j < 4; j++) {
            int cc = col0 + wn * 32 + j * 8 + tc;
            float b0 = bias ? bias[cc] : 0.f;
            float b1 = bias ? bias[cc + 1] : 0.f;
            if (rb < M) {
                float2 v = make_float2(acc[i][j][0] + b0, acc[i][j][1] + b1);
                *reinterpret_cast<float2*>(C + (size_t)rb * NI + cc) = v;
            }
            if (rb + 8 < M) {
                float2 v = make_float2(acc[i][j][2] + b0, acc[i][j][3] + b1);
                *reinterpret_cast<float2*>(C + (size_t)(rb + 8) * NI + cc) = v;
            }
        }
    }
}

// ---------------------------------------------------------------------------
// Weight split: W fp32 -> (hi, lo) bf16.
// ---------------------------------------------------------------------------
__global__ void wsplit_kernel(const float* __restrict__ W,
                              __nv_bfloat16* __restrict__ hi,
                              __nv_bfloat16* __restrict__ lo) {
    int i = (blockIdx.x * 256 + threadIdx.x) * 4;
    float4 w = *reinterpret_cast<const float4*>(W + i);
    __nv_bfloat16 h0 = __float2bfloat16(w.x), h1 = __float2bfloat16(w.y);
    __nv_bfloat16 h2 = __float2bfloat16(w.z), h3 = __float2bfloat16(w.w);
    __nv_bfloat162 hh0 = {h0, h1}, hh1 = {h2, h3};
    *reinterpret_cast<__nv_bfloat162*>(hi + i)     = hh0;
    *reinterpret_cast<__nv_bfloat162*>(hi + i + 2) = hh1;
    __nv_bfloat162 ll0 = {__float2bfloat16(w.x - __bfloat162float(h0)),
                          __float2bfloat16(w.y - __bfloat162float(h1))};
    __nv_bfloat162 ll1 = {__float2bfloat16(w.z - __bfloat162float(h2)),
                          __float2bfloat16(w.w - __bfloat162float(h3))};
    *reinterpret_cast<__nv_bfloat162*>(lo + i)     = ll0;
    *reinterpret_cast<__nv_bfloat162*>(lo + i + 2) = ll1;
}

__device__ __forceinline__ void store_hilo(__nv_bfloat16* hi, __nv_bfloat16* lo,
                                           size_t idx, float x) {
    __nv_bfloat16 h = __float2bfloat16(x);
    hi[idx] = h;
    lo[idx] = __float2bfloat16(x - __bfloat162float(h));
}

// ---------------------------------------------------------------------------
// K1: Gram + clamp + LN + LeakyReLU -> bf16 hi/lo.
// ---------------------------------------------------------------------------
__global__ void gram_ln_lrelu_kernel(const float* __restrict__ V,
                                     const float* __restrict__ g,
                                     const float* __restrict__ b,
                                     __nv_bfloat16* __restrict__ Xhi,
                                     __nv_bfloat16* __restrict__ Xlo, int m) {
    int n = blockIdx.x;
    const float* v = V + (size_t)n * 32 * m;
    __shared__ float vs[96];
    __shared__ float red[16];
    int tid = threadIdx.x;
    if (tid < 32 * m) vs[tid] = v[tid];
    __syncthreads();

    float vals[4];
    float s = 0.f, s2 = 0.f;
#pragma unroll
    for (int i = 0; i < 4; i++) {
        int e = tid + i * 256;
        int a = e >> 5, c = e & 31;
        float d = 0.f;
        for (int k = 0; k < m; k++) d += vs[a * m + k] * vs[c * m + k];
        if (d > 0.f)      d = fmaxf(d, 1e-12f);
        else if (d < 0.f) d = fminf(d, -1e-12f);
        vals[i] = d;
        s += d; s2 += d * d;
    }
#pragma unroll
    for (int o = 16; o > 0; o >>= 1) {
        s  += __shfl_xor_sync(0xffffffffu, s,  o);
        s2 += __shfl_xor_sync(0xffffffffu, s2, o);
    }
    if ((tid & 31) == 0) { red[tid >> 5] = s; red[8 + (tid >> 5)] = s2; }
    __syncthreads();
    if (tid < 32) {
        float a0 = (tid < 8) ? red[tid] : 0.f;
        float a1 = (tid < 8) ? red[8 + tid] : 0.f;
#pragma unroll
        for (int o = 4; o > 0; o >>= 1) {
            a0 += __shfl_xor_sync(0xffffffffu, a0, o);
            a1 += __shfl_xor_sync(0xffffffffu, a1, o);
        }
        if (tid == 0) { red[0] = a0; red[1] = a1; }
    }
    __syncthreads();
    float mean = red[0] * (1.f / NI);
    float var  = red[1] * (1.f / NI) - mean * mean;
    float rstd = rsqrtf(var + LN_EPS);
#pragma unroll
    for (int i = 0; i < 4; i++) {
        int e = tid + i * 256;
        float x = (vals[i] - mean) * rstd * g[e] + b[e];
        x = (x >= 0.f) ? x : SLOPE * x;
        store_hilo(Xhi, Xlo, (size_t)n * NI + e, x);
    }
}

// ---------------------------------------------------------------------------
// K3: LayerNorm + LeakyReLU (fp32 in) -> bf16 hi/lo.
// ---------------------------------------------------------------------------
__global__ void ln_lrelu_kernel(const float* __restrict__ in,
                                const float* __restrict__ g,
                                const float* __restrict__ b,
                                __nv_bfloat16* __restrict__ Xhi,
                                __nv_bfloat16* __restrict__ Xlo) {
    int n = blockIdx.x;
    int tid = threadIdx.x;
    __shared__ float red[16];
    const float* row = in + (size_t)n * NI;

    float vals[4];
    float s = 0.f, s2 = 0.f;
#pragma unroll
    for (int i = 0; i < 4; i++) {
        float d = row[tid + i * 256];
        vals[i] = d;
        s += d; s2 += d * d;
    }
#pragma unroll
    for (int o = 16; o > 0; o >>= 1) {
        s  += __shfl_xor_sync(0xffffffffu, s,  o);
        s2 += __shfl_xor_sync(0xffffffffu, s2, o);
    }
    if ((tid & 31) == 0) { red[tid >> 5] = s; red[8 + (tid >> 5)] = s2; }
    __syncthreads();
    if (tid < 32) {
        float a0 = (tid < 8) ? red[tid] : 0.f;
        float a1 = (tid < 8) ? red[8 + tid] : 0.f;
#pragma unroll
        for (int o = 4; o > 0; o >>= 1) {
            a0 += __shfl_xor_sync(0xffffffffu, a0, o);
            a1 += __shfl_xor_sync(0xffffffffu, a1, o);
        }
        if (tid == 0) { red[0] = a0; red[1] = a1; }
    }
    __syncthreads();
    float mean = red[0] * (1.f / NI);
    float var  = red[1] * (1.f / NI) - mean * mean;
    float rstd = rsqrtf(var + LN_EPS);
#pragma unroll
    for (int i = 0; i < 4; i++) {
        int e = tid + i * 256;
        float x = (vals[i] - mean) * rstd * g[e] + b[e];
        x = (x >= 0.f) ? x : SLOPE * x;
        store_hilo(Xhi, Xlo, (size_t)n * NI + e, x);
    }
}

// ---------------------------------------------------------------------------
// K5: softmax over 32 groups of 32 + attn @ v.
// ---------------------------------------------------------------------------
__global__ void softmax_out_kernel(const float* __restrict__ H,
                                   const float* __restrict__ V,
                                   float* __restrict__ out, int m) {
    int n = blockIdx.x;
    __shared__ float vs[96];
    int tid = threadIdx.x, w = tid >> 5, lane = tid & 31;
    if (tid < 32 * m) vs[tid] = V[(size_t)n * 32 * m + tid];
    __syncthreads();
    const float* h = H + (size_t)n * NI;
#pragma unroll
    for (int it = 0; it < 4; it++) {
        int a = w + it * 8;
        float x = h[a * 32 + lane];
        float mx = x;
#pragma unroll
        for (int o = 16; o > 0; o >>= 1)
            mx = fmaxf(mx, __shfl_xor_sync(0xffffffffu, mx, o));
        float e = __expf(x - mx);
        float sum = e;
#pragma unroll
        for (int o = 16; o > 0; o >>= 1)
            sum += __shfl_xor_sync(0xffffffffu, sum, o);
        float p = e / sum;
        for (int k = 0; k < m; k++) {
            float t = p * vs[lane * m + k];
#pragma unroll
            for (int o = 16; o > 0; o >>= 1)
                t += __shfl_xor_sync(0xffffffffu, t, o);
            if (lane == 0) out[(size_t)n * 32 * m + a * m + k] = t;
        }
    }
}

// ---------------------------------------------------------------------------
// Launch
// ---------------------------------------------------------------------------
extern "C" void kernel_launch(void* const* d_in, const int* in_sizes, int n_in,
                              void* d_out, int out_size) {
    const float* f0 = (const float*)d_in[0];
    const float* f1 = (const float*)d_in[1];
    const float* ln1_g_0 = (const float*)d_in[2];
    const float* ln1_b_0 = (const float*)d_in[3];
    const float* w1_0    = (const float*)d_in[4];
    const float* ln2_g_0 = (const float*)d_in[5];
    const float* ln2_b_0 = (const float*)d_in[6];
    const float* w2_0    = (const float*)d_in[7];
    const float* b2_0    = (const float*)d_in[8];
    const float* ln1_g_1 = (const float*)d_in[9];
    const float* ln1_b_1 = (const float*)d_in[10];
    const float* w1_1    = (const float*)d_in[11];
    const float* ln2_g_1 = (const float*)d_in[12];
    const float* ln2_b_1 = (const float*)d_in[13];
    const float* w2_1    = (const float*)d_in[14];
    const float* b2_1    = (const float*)d_in[15];

    float* out = (float*)d_out;

    __nv_bfloat16 *xhi, *xlo, *whi, *wlo;
    float* hbuf;
    cudaGetSymbolAddress((void**)&xhi, g_Xhi);
    cudaGetSymbolAddress((void**)&xlo, g_Xlo);
    cudaGetSymbolAddress((void**)&whi, g_Whi);
    cudaGetSymbolAddress((void**)&wlo, g_Wlo);
    cudaGetSymbolAddress((void**)&hbuf, g_H);

    cudaFuncSetAttribute(gemm_mma_kernel,
                         cudaFuncAttributeMaxDynamicSharedMemorySize, SMEM_TOTAL);

    dim3 gemm_grid(NI / BN, (NROWS + BM - 1) / BM);

    // ---- type 0 (m = 1) ----
    wsplit_kernel<<<NI * NI / 1024, 256>>>(w1_0, whi, wlo);
    gram_ln_lrelu_kernel<<<NROWS, 256>>>(f0, ln1_g_0, ln1_b_0, xhi, xlo, 1);
    gemm_mma_kernel<<<gemm_grid, 256, SMEM_TOTAL>>>(xhi, xlo, whi, wlo, nullptr, hbuf, NROWS);
    wsplit_kernel<<<NI * NI / 1024, 256>>>(w2_0, whi, wlo);
    ln_lrelu_kernel<<<NROWS, 256>>>(hbuf, ln2_g_0, ln2_b_0, xhi, xlo);
    gemm_mma_kernel<<<gemm_grid, 256, SMEM_TOTAL>>>(xhi, xlo, whi, wlo, b2_0, hbuf, NROWS);
    softmax_out_kernel<<<NROWS, 256>>>(hbuf, f0, out, 1);

    // ---- type 1 (m = 3) ----
    wsplit_kernel<<<NI * NI / 1024, 256>>>(w1_1, whi, wlo);
    gram_ln_lrelu_kernel<<<NROWS, 256>>>(f1, ln1_g_1, ln1_b_1, xhi, xlo, 3);
    gemm_mma_kernel<<<gemm_grid, 256, SMEM_TOTAL>>>(xhi, xlo, whi, wlo, nullptr, hbuf, NROWS);
    wsplit_kernel<<<NI * NI / 1024, 256>>>(w2_1, whi, wlo);
    ln_lrelu_kernel<<<NROWS, 256>>>(hbuf, ln2_g_1, ln2_b_1, xhi, xlo);
    gemm_mma_kernel<<<gemm_grid, 256, SMEM_TOTAL>>>(xhi, xlo, whi, wlo, b2_1, hbuf, NROWS);
    softmax_out_kernel<<<NROWS, 256>>>(hbuf, f1, out + (size_t)NROWS * 32, 3);
}